// round 4
// baseline (speedup 1.0000x reference)
#include <cuda_runtime.h>
#include <math_constants.h>

#define N 384
#define D 128
#define MARGIN 0.2f
#define RHO 10.0f
#define GA 3                  // anchors per block
#define NBLK (N / GA)         // 128 blocks = one wave
#define NT 384                // one thread per row k
#define NWARP (NT / 32)       // 12

__device__ double g_num;
__device__ int    g_den;
__device__ int    g_count;    // zero-init; last block resets each replay

__global__ void __launch_bounds__(NT, 1)
facenet_kernel(const int* __restrict__ classes,
               const float* __restrict__ emb,
               float* __restrict__ out) {
    __shared__ float  anc[GA][D];
    __shared__ float  drow[GA][N];    // dots, then raw distances
    __shared__ float  dval[GA][N];    // valid-negative distances (else +INF)
    __shared__ float  sqv[N];
    __shared__ int    cls[N];
    __shared__ short  poslist[GA][N];
    __shared__ int    npos[GA];
    __shared__ double warpsum[NWARP];
    __shared__ bool   islast;

    const int tid  = threadIdx.x;     // == row k
    const int base = blockIdx.x * GA;

    // ---- load anchors + classes ----
    for (int idx = tid; idx < GA * D; idx += NT)
        anc[idx >> 7][idx & (D - 1)] = emb[(base + (idx >> 7)) * D + (idx & (D - 1))];
    cls[tid] = classes[tid];
    if (tid < GA) npos[tid] = 0;
    __syncthreads();

    // ---- dots of row k with the 3 anchors, plus ||k||^2 ----
    {
        const float4* rowk = reinterpret_cast<const float4*>(emb + tid * D);
        const float4* a0 = reinterpret_cast<const float4*>(anc[0]);
        const float4* a1 = reinterpret_cast<const float4*>(anc[1]);
        const float4* a2 = reinterpret_cast<const float4*>(anc[2]);
        float d0 = 0.f, d1 = 0.f, d2 = 0.f, sq = 0.f;
#pragma unroll
        for (int q = 0; q < D / 4; q++) {
            float4 v = rowk[q];
            float4 w0 = a0[q], w1 = a1[q], w2 = a2[q];
            sq = fmaf(v.x, v.x, fmaf(v.y, v.y, fmaf(v.z, v.z, fmaf(v.w, v.w, sq))));
            d0 = fmaf(v.x, w0.x, fmaf(v.y, w0.y, fmaf(v.z, w0.z, fmaf(v.w, w0.w, d0))));
            d1 = fmaf(v.x, w1.x, fmaf(v.y, w1.y, fmaf(v.z, w1.z, fmaf(v.w, w1.w, d1))));
            d2 = fmaf(v.x, w2.x, fmaf(v.y, w2.y, fmaf(v.z, w2.z, fmaf(v.w, w2.w, d2))));
        }
        drow[0][tid] = d0; drow[1][tid] = d1; drow[2][tid] = d2;
        sqv[tid] = sq;
    }
    __syncthreads();

    // ---- distances, masked arrays, positive-pair lists ----
    {
        const int k  = tid;
        const float sqk = sqv[k];
        const int  ck  = cls[k];
#pragma unroll
        for (int g = 0; g < GA; g++) {
            const int a = base + g;
            float dist = fmaxf(sqv[a] + sqk - 2.0f * drow[g][k], 0.0f);
            drow[g][k] = dist;
            bool same = (ck == cls[a]);
            dval[g][k] = same ? CUDART_INF_F : dist;   // valid negatives only
            if (same && k != a) {
                int p = atomicAdd(&npos[g], 1);
                poslist[g][p] = (short)k;
            }
        }
    }
    __syncthreads();

    const int np0 = npos[0], np1 = npos[1], np2 = npos[2];
    const int ntot = np0 + np1 + np2;
    if (tid == 0 && ntot > 0) atomicAdd(&g_den, ntot);

    // ---- per-pair scans: warp per pair ----
    const int warp = tid >> 5;
    const int lane = tid & 31;
    double wsum = 0.0;

    for (int p = warp; p < ntot; p += NWARP) {
        int g, l;
        if (p < np0)            { g = 0; l = p; }
        else if (p < np0 + np1) { g = 1; l = p - np0; }
        else                    { g = 2; l = p - np0 - np1; }

        const float t = drow[g][poslist[g][l]];   // d(i, j)
        const float* dv = dval[g];

        float minw = CUDART_INF_F;    // min x in [0, MARGIN)
        float maxn = -CUDART_INF_F;   // max x < 0
#pragma unroll
        for (int kk = 0; kk < N / 32; kk++) {
            float x = dv[kk * 32 + lane] - t;     // d(i,k) - d(i,j)
            minw = fminf(minw, (x >= 0.0f && x < MARGIN) ? x : CUDART_INF_F);
            maxn = fmaxf(maxn, (x < 0.0f) ? x : -CUDART_INF_F);
        }
#pragma unroll
        for (int off = 16; off; off >>= 1) {
            minw = fminf(minw, __shfl_xor_sync(0xffffffffu, minw, off));
            maxn = fmaxf(maxn, __shfl_xor_sync(0xffffffffu, maxn, off));
        }
        // semihard: loss = MARGIN - x for x in [0, MARGIN) -> max = MARGIN - minw
        float semimax = (minw < CUDART_INF_F) ? (MARGIN - minw) : 0.0f;
        // hard: min loss = MARGIN - maxn (> MARGIN); contributes iff < RHO
        float minhard = MARGIN - maxn;            // +INF if no hard k
        float pph = (minhard < RHO) ? minhard : 0.0f;
        wsum += (double)((semimax > 0.0f) ? semimax : pph);
    }

    if (lane == 0) warpsum[warp] = wsum;
    __syncthreads();

    if (tid == 0) {
        double s = 0.0;
#pragma unroll
        for (int w = 0; w < NWARP; w++) s += warpsum[w];
        if (s != 0.0) atomicAdd(&g_num, s);
        __threadfence();
        int c = atomicAdd(&g_count, 1);
        islast = (c == NBLK - 1);
    }
    __syncthreads();

    // ---- last block finalizes + resets for the next graph replay ----
    if (islast && tid == 0) {
        double num = atomicAdd(&g_num, 0.0);      // fenced read
        int    den = atomicAdd(&g_den, 0);
        double r = (den > 0) ? (num / fmax((double)den, 1.0)) : 0.0;
        out[0] = (float)r;
        g_num = 0.0;
        g_den = 0;
        __threadfence();
        g_count = 0;
    }
}

extern "C" void kernel_launch(void* const* d_in, const int* in_sizes, int n_in,
                              void* d_out, int out_size) {
    const int*   classes = (const int*)d_in[0];
    const float* emb     = (const float*)d_in[1];
    facenet_kernel<<<NBLK, NT>>>(classes, emb, (float*)d_out);
}